// round 2
// baseline (speedup 1.0000x reference)
#include <cuda_runtime.h>
#include <cuda_bf16.h>

// Problem constants (fixed by setup_inputs of SynchronizationLoss_79431125172891)
#define N_TRIALS   8
#define T_TOTAL    600
#define N_NEURONS  30000
#define T_USE      500      // T_END_MS - T_START_MS
#define N_SAMPLES  50
#define MAX_COUNT  200
#define N_BINS     16
#define EPS        1e-7f
#define SYNC_COST  10.0f

// BIN_MS from logspace(-3,0,20), cutoff < 0.25, rounded to ms
__constant__ int c_bins[N_BINS] = {1,1,2,3,4,6,9,13,18,26,38,55,78,113,162,234};

// Scratch: sel[s][t]  (population counts per sample per timestep)
__device__ float g_sel[N_SAMPLES * T_USE];

// ---------------------------------------------------------------------------
// Phase 1: gather-sum.  One thread owns one (sample, t) output.
// Block = (sample s, t-chunk); smem holds this sample's neuron ids.
// mask is prefix-form (arange < count), so effective count = sum(mask) and
// the first `cnt` ids are exactly the active ones (duplicates preserved).
// NOTE: sample_ids is int32 on device (JAX x64-disabled demotes int64->int32).
// ---------------------------------------------------------------------------
__global__ void __launch_bounds__(128)
gather_kernel(const float* __restrict__ spikes,
              const int*   __restrict__ trials,
              const int*   __restrict__ ids,
              const float* __restrict__ mask)
{
    __shared__ int s_ids[MAX_COUNT];
    __shared__ int s_cnt;

    const int s   = blockIdx.x;
    const int tid = threadIdx.x;

    if (tid == 0) s_cnt = 0;
    __syncthreads();

    int local = 0;
    for (int j = tid; j < MAX_COUNT; j += blockDim.x) {
        s_ids[j] = ids[s * MAX_COUNT + j];
        if (mask[s * MAX_COUNT + j] != 0.0f) local++;
    }
    if (local) atomicAdd(&s_cnt, local);
    __syncthreads();

    const int cnt = s_cnt;
    const int t   = blockIdx.y * blockDim.x + tid;
    if (t >= T_USE) return;

    const float* __restrict__ base =
        spikes + (size_t)trials[s] * ((size_t)T_TOTAL * N_NEURONS)
               + (size_t)t * N_NEURONS;

    float acc = 0.0f;
    int j = 0;
    // 8-wide unroll: 8 independent scattered LDGs in flight per thread (MLP).
    for (; j + 8 <= cnt; j += 8) {
        float v0 = __ldg(base + s_ids[j + 0]);
        float v1 = __ldg(base + s_ids[j + 1]);
        float v2 = __ldg(base + s_ids[j + 2]);
        float v3 = __ldg(base + s_ids[j + 3]);
        float v4 = __ldg(base + s_ids[j + 4]);
        float v5 = __ldg(base + s_ids[j + 5]);
        float v6 = __ldg(base + s_ids[j + 6]);
        float v7 = __ldg(base + s_ids[j + 7]);
        acc += ((v0 + v1) + (v2 + v3)) + ((v4 + v5) + (v6 + v7));
    }
    for (; j < cnt; ++j) acc += __ldg(base + s_ids[j]);

    g_sel[s * T_USE + t] = acc;
}

// ---------------------------------------------------------------------------
// Phase 2: Fano factors per (bin, sample), mean over samples, MSE, scale.
// One block, 800 tasks. Two-pass mean/variance (matches jnp.var ddof=0).
// ---------------------------------------------------------------------------
__global__ void __launch_bounds__(256)
fano_kernel(const float* __restrict__ exp_fanos, float* __restrict__ out)
{
    __shared__ float s_fano[N_BINS];
    const int tid = threadIdx.x;
    if (tid < N_BINS) s_fano[tid] = 0.0f;
    __syncthreads();

    for (int task = tid; task < N_BINS * N_SAMPLES; task += blockDim.x) {
        const int b  = task / N_SAMPLES;
        const int s  = task % N_SAMPLES;
        const int bs = c_bins[b];
        const int nb = T_USE / bs;
        const int tt = nb * bs;
        const float* __restrict__ row = g_sel + s * T_USE;

        // pass 1: mean of binned counts = (sum over used window) / nb
        float total = 0.0f;
        for (int t = 0; t < tt; ++t) total += row[t];
        const float mean = total / (float)nb;

        // pass 2: population variance of binned counts
        float var = 0.0f;
        for (int k = 0; k < nb; ++k) {
            float c = 0.0f;
            const float* rk = row + k * bs;
            for (int u = 0; u < bs; ++u) c += rk[u];
            const float d = c - mean;
            var += d * d;
        }
        var /= (float)nb;

        const float fano = var / fmaxf(mean, EPS);
        atomicAdd(&s_fano[b], fano);
    }
    __syncthreads();

    if (tid == 0) {
        float mse = 0.0f;
        for (int b = 0; b < N_BINS; ++b) {
            const float fm = s_fano[b] / (float)N_SAMPLES;
            const float d  = exp_fanos[b] - fm;
            mse += d * d;
        }
        out[0] = SYNC_COST * (mse / (float)N_BINS);
    }
}

// ---------------------------------------------------------------------------
// Inputs (metadata order):
//   0: spikes  float32  [8, 600, 30000]
//   1: experimental_fanos_mean float32 [16]
//   2: sample_trials int32 [50]
//   3: sample_ids    int32 [50, 200]   (JAX demotes int64 -> int32)
//   4: sample_mask   float32 [50, 200]
// Output: float32 scalar
// ---------------------------------------------------------------------------
extern "C" void kernel_launch(void* const* d_in, const int* in_sizes, int n_in,
                              void* d_out, int out_size)
{
    const float* spikes = (const float*)d_in[0];
    const float* expf_  = (const float*)d_in[1];
    const int*   trials = (const int*)d_in[2];
    const int*   ids    = (const int*)d_in[3];
    const float* mask   = (const float*)d_in[4];
    float*       out    = (float*)d_out;

    dim3 grid(N_SAMPLES, (T_USE + 127) / 128);
    gather_kernel<<<grid, 128>>>(spikes, trials, ids, mask);
    fano_kernel<<<1, 256>>>(expf_, out);
}

// round 3
// speedup vs baseline: 4.2096x; 4.2096x over previous
#include <cuda_runtime.h>
#include <cuda_bf16.h>

#define N_TRIALS   8
#define T_TOTAL    600
#define N_NEURONS  30000
#define T_USE      500
#define N_SAMPLES  50
#define MAX_COUNT  200
#define N_BINS     16
#define EPS        1e-7f
#define SYNC_COST  10.0f

#define NJ         4            // id-range chunks for gather parallelism
#define JCHUNK     (MAX_COUNT / NJ)   // 50

__constant__ int c_bins[N_BINS] = {1,1,2,3,4,6,9,13,18,26,38,55,78,113,162,234};

// Scratch (device globals: no allocation allowed)
__device__ float g_part[NJ * N_SAMPLES * T_USE];   // partial gather sums
__device__ float g_sel [N_SAMPLES * T_USE];        // combined sel[s][t]
__device__ float g_fano[N_BINS * N_SAMPLES];       // per-(bin,sample) fano

// ---------------------------------------------------------------------------
// Phase 1: gather partial sums. Block = (sample, t-chunk, j-chunk).
// mask is prefix-form, so effective count = sum(mask); ids[0:cnt] are active.
// sample_ids arrives as int32 (JAX x64-disabled demotes int64).
// ---------------------------------------------------------------------------
__global__ void __launch_bounds__(128)
gather_kernel(const float* __restrict__ spikes,
              const int*   __restrict__ trials,
              const int*   __restrict__ ids,
              const float* __restrict__ mask)
{
    __shared__ int s_ids[JCHUNK];
    __shared__ int s_cnt;

    const int s   = blockIdx.x;
    const int jc  = blockIdx.z;
    const int tid = threadIdx.x;

    if (tid == 0) s_cnt = 0;
    __syncthreads();

    // effective count (full mask) + this chunk's ids into smem
    int local = 0;
    for (int j = tid; j < MAX_COUNT; j += blockDim.x)
        if (mask[s * MAX_COUNT + j] != 0.0f) local++;
    if (tid < JCHUNK)
        s_ids[tid] = ids[s * MAX_COUNT + jc * JCHUNK + tid];
    if (local) atomicAdd(&s_cnt, local);
    __syncthreads();

    const int cnt = s_cnt;
    const int lo  = jc * JCHUNK;
    const int m   = min(cnt - lo, JCHUNK);   // elements in this chunk (may be <=0)

    const int t = blockIdx.y * blockDim.x + tid;
    if (t >= T_USE) return;

    float acc = 0.0f;
    if (m > 0) {
        const float* __restrict__ base =
            spikes + (size_t)trials[s] * ((size_t)T_TOTAL * N_NEURONS)
                   + (size_t)t * N_NEURONS;
        int j = 0;
        for (; j + 8 <= m; j += 8) {
            float v0 = __ldg(base + s_ids[j + 0]);
            float v1 = __ldg(base + s_ids[j + 1]);
            float v2 = __ldg(base + s_ids[j + 2]);
            float v3 = __ldg(base + s_ids[j + 3]);
            float v4 = __ldg(base + s_ids[j + 4]);
            float v5 = __ldg(base + s_ids[j + 5]);
            float v6 = __ldg(base + s_ids[j + 6]);
            float v7 = __ldg(base + s_ids[j + 7]);
            acc += ((v0 + v1) + (v2 + v3)) + ((v4 + v5) + (v6 + v7));
        }
        for (; j < m; ++j) acc += __ldg(base + s_ids[j]);
    }
    g_part[(jc * N_SAMPLES + s) * T_USE + t] = acc;
}

// ---------------------------------------------------------------------------
// Phase 2: combine the NJ partials into g_sel.
// ---------------------------------------------------------------------------
__global__ void __launch_bounds__(256)
combine_kernel()
{
    const int i = blockIdx.x * blockDim.x + threadIdx.x;
    if (i < N_SAMPLES * T_USE) {
        float v = g_part[i];
        #pragma unroll
        for (int c = 1; c < NJ; ++c)
            v += g_part[c * N_SAMPLES * T_USE + i];
        g_sel[i] = v;
    }
}

// ---------------------------------------------------------------------------
// Phase 3: one warp per (bin, sample) task. Lanes own bins round-robin;
// single-pass sum / sum-of-squares, warp shfl reduce.
// ---------------------------------------------------------------------------
__global__ void __launch_bounds__(32)
fano_kernel()
{
    const int task = blockIdx.x;               // 0 .. N_BINS*N_SAMPLES-1
    const int lane = threadIdx.x;
    const int b    = task / N_SAMPLES;
    const int s    = task % N_SAMPLES;
    const int bs   = c_bins[b];
    const int nb   = T_USE / bs;
    const float* __restrict__ row = g_sel + s * T_USE;

    float sum = 0.0f, sumsq = 0.0f;
    for (int k = lane; k < nb; k += 32) {
        const float* rk = row + k * bs;
        float c = 0.0f;
        int u = 0;
        for (; u + 4 <= bs; u += 4) {
            float a0 = rk[u], a1 = rk[u+1], a2 = rk[u+2], a3 = rk[u+3];
            c += (a0 + a1) + (a2 + a3);
        }
        for (; u < bs; ++u) c += rk[u];
        sum   += c;
        sumsq += c * c;
    }
    #pragma unroll
    for (int off = 16; off > 0; off >>= 1) {
        sum   += __shfl_down_sync(0xffffffff, sum,   off);
        sumsq += __shfl_down_sync(0xffffffff, sumsq, off);
    }
    if (lane == 0) {
        const float mean = sum / (float)nb;
        const float var  = sumsq / (float)nb - mean * mean;
        g_fano[task] = var / fmaxf(mean, EPS);
    }
}

// ---------------------------------------------------------------------------
// Phase 4: per-bin mean over samples, MSE vs experimental, scale. One warp.
// ---------------------------------------------------------------------------
__global__ void __launch_bounds__(32)
final_kernel(const float* __restrict__ exp_fanos, float* __restrict__ out)
{
    const int lane = threadIdx.x;
    float d2 = 0.0f;
    if (lane < N_BINS) {
        float sum = 0.0f;
        for (int s = 0; s < N_SAMPLES; ++s)
            sum += g_fano[lane * N_SAMPLES + s];
        const float fm = sum / (float)N_SAMPLES;
        const float d  = exp_fanos[lane] - fm;
        d2 = d * d;
    }
    #pragma unroll
    for (int off = 16; off > 0; off >>= 1)
        d2 += __shfl_down_sync(0xffffffff, d2, off);
    if (lane == 0)
        out[0] = SYNC_COST * (d2 / (float)N_BINS);
}

// ---------------------------------------------------------------------------
// Inputs (metadata order):
//   0: spikes float32 [8,600,30000]   1: experimental_fanos_mean float32 [16]
//   2: sample_trials int32 [50]       3: sample_ids int32 [50,200]
//   4: sample_mask float32 [50,200]   out: float32 scalar
// ---------------------------------------------------------------------------
extern "C" void kernel_launch(void* const* d_in, const int* in_sizes, int n_in,
                              void* d_out, int out_size)
{
    const float* spikes = (const float*)d_in[0];
    const float* expf_  = (const float*)d_in[1];
    const int*   trials = (const int*)d_in[2];
    const int*   ids    = (const int*)d_in[3];
    const float* mask   = (const float*)d_in[4];
    float*       out    = (float*)d_out;

    dim3 grid(N_SAMPLES, (T_USE + 127) / 128, NJ);
    gather_kernel<<<grid, 128>>>(spikes, trials, ids, mask);
    combine_kernel<<<(N_SAMPLES * T_USE + 255) / 256, 256>>>();
    fano_kernel<<<N_BINS * N_SAMPLES, 32>>>();
    final_kernel<<<1, 32>>>(expf_, out);
}

// round 4
// speedup vs baseline: 4.5439x; 1.0794x over previous
#include <cuda_runtime.h>
#include <cuda_bf16.h>

#define N_TRIALS   8
#define T_TOTAL    600
#define N_NEURONS  30000
#define T_USE      500
#define N_SAMPLES  50
#define MAX_COUNT  200
#define N_BINS     16
#define EPS        1e-7f
#define SYNC_COST  10.0f

#define NJ         8                 // id-range chunks for gather parallelism
#define JCHUNK     (MAX_COUNT / NJ)  // 25

__constant__ int c_bins[N_BINS] = {1,1,2,3,4,6,9,13,18,26,38,55,78,113,162,234};

// Scratch (device globals: allocation is forbidden)
__device__ float        g_part[NJ * N_SAMPLES * T_USE];  // partial gather sums
__device__ float        g_fano[N_BINS * N_SAMPLES];      // per-(bin,sample) fano
__device__ unsigned int g_ticket;                        // last-block ticket (self-resetting)

// ---------------------------------------------------------------------------
// Phase 1: gather partial sums. Block = (sample, t-chunk, j-chunk).
// mask is prefix-form (arange < count) => effective count = sum(mask), and
// ids[0:cnt] are exactly the active ids (duplicates preserved).
// sample_ids arrives as int32 (JAX x64-disabled demotes int64 -> int32).
// ---------------------------------------------------------------------------
__global__ void __launch_bounds__(128)
gather_kernel(const float* __restrict__ spikes,
              const int*   __restrict__ trials,
              const int*   __restrict__ ids,
              const float* __restrict__ mask)
{
    __shared__ int s_ids[JCHUNK];
    __shared__ int s_cnt;

    const int s   = blockIdx.x;
    const int jc  = blockIdx.z;
    const int tid = threadIdx.x;

    if (tid == 0) s_cnt = 0;
    __syncthreads();

    int local = 0;
    for (int j = tid; j < MAX_COUNT; j += blockDim.x)
        if (mask[s * MAX_COUNT + j] != 0.0f) local++;
    if (tid < JCHUNK)
        s_ids[tid] = ids[s * MAX_COUNT + jc * JCHUNK + tid];
    if (local) atomicAdd(&s_cnt, local);
    __syncthreads();

    const int cnt = s_cnt;
    const int m   = min(cnt - jc * JCHUNK, JCHUNK);  // elems in this chunk (may be <=0)

    const int t = blockIdx.y * blockDim.x + tid;
    if (t >= T_USE) return;

    float acc = 0.0f;
    if (m > 0) {
        const float* __restrict__ base =
            spikes + (size_t)trials[s] * ((size_t)T_TOTAL * N_NEURONS)
                   + (size_t)t * N_NEURONS;
        int j = 0;
        for (; j + 8 <= m; j += 8) {
            float v0 = __ldg(base + s_ids[j + 0]);
            float v1 = __ldg(base + s_ids[j + 1]);
            float v2 = __ldg(base + s_ids[j + 2]);
            float v3 = __ldg(base + s_ids[j + 3]);
            float v4 = __ldg(base + s_ids[j + 4]);
            float v5 = __ldg(base + s_ids[j + 5]);
            float v6 = __ldg(base + s_ids[j + 6]);
            float v7 = __ldg(base + s_ids[j + 7]);
            acc += ((v0 + v1) + (v2 + v3)) + ((v4 + v5) + (v6 + v7));
        }
        for (; j < m; ++j) acc += __ldg(base + s_ids[j]);
    }
    g_part[(jc * N_SAMPLES + s) * T_USE + t] = acc;
}

// ---------------------------------------------------------------------------
// Phase 2 (fused): one block per sample.
//   - combine NJ partials into an smem row (fixed order -> deterministic)
//   - 8 warps x 2 bins: single-pass sum/sumsq -> fano per (bin, sample)
//   - last block to finish computes per-bin means, MSE, scales, writes out,
//     and resets the ticket for the next graph replay.
// ---------------------------------------------------------------------------
__global__ void __launch_bounds__(256)
fano_kernel(const float* __restrict__ exp_fanos, float* __restrict__ out)
{
    __shared__ float s_row[T_USE];
    __shared__ bool  s_last;

    const int s    = blockIdx.x;
    const int tid  = threadIdx.x;
    const int wid  = tid >> 5;
    const int lane = tid & 31;

    // combine partials into smem row
    for (int i = tid; i < T_USE; i += blockDim.x) {
        float v = 0.0f;
        #pragma unroll
        for (int c = 0; c < NJ; ++c)
            v += g_part[(c * N_SAMPLES + s) * T_USE + i];
        s_row[i] = v;
    }
    __syncthreads();

    // two bins per warp: wid and wid+8
    #pragma unroll
    for (int rep = 0; rep < 2; ++rep) {
        const int b  = wid + rep * 8;
        const int bs = c_bins[b];
        const int nb = T_USE / bs;

        float sum = 0.0f, sumsq = 0.0f;
        for (int k = lane; k < nb; k += 32) {
            const float* rk = s_row + k * bs;
            float c = 0.0f;
            int u = 0;
            for (; u + 4 <= bs; u += 4) {
                float a0 = rk[u], a1 = rk[u+1], a2 = rk[u+2], a3 = rk[u+3];
                c += (a0 + a1) + (a2 + a3);
            }
            for (; u < bs; ++u) c += rk[u];
            sum   += c;
            sumsq += c * c;
        }
        #pragma unroll
        for (int off = 16; off > 0; off >>= 1) {
            sum   += __shfl_down_sync(0xffffffff, sum,   off);
            sumsq += __shfl_down_sync(0xffffffff, sumsq, off);
        }
        if (lane == 0) {
            const float mean = sum / (float)nb;
            const float var  = sumsq / (float)nb - mean * mean;
            g_fano[b * N_SAMPLES + s] = var / fmaxf(mean, EPS);
        }
    }

    // last-block: reduce g_fano -> scalar loss
    __threadfence();
    __syncthreads();
    if (tid == 0) {
        unsigned int old = atomicAdd(&g_ticket, 1u);
        s_last = (old == N_SAMPLES - 1);
    }
    __syncthreads();

    if (s_last) {
        if (tid == 0) g_ticket = 0;     // reset for next graph replay
        __threadfence();
        if (wid == 0) {
            float d2 = 0.0f;
            if (lane < N_BINS) {
                float fsum = 0.0f;
                for (int q = 0; q < N_SAMPLES; ++q)
                    fsum += g_fano[lane * N_SAMPLES + q];
                const float fm = fsum / (float)N_SAMPLES;
                const float d  = exp_fanos[lane] - fm;
                d2 = d * d;
            }
            #pragma unroll
            for (int off = 16; off > 0; off >>= 1)
                d2 += __shfl_down_sync(0xffffffff, d2, off);
            if (lane == 0)
                out[0] = SYNC_COST * (d2 / (float)N_BINS);
        }
    }
}

// ---------------------------------------------------------------------------
// Inputs (metadata order):
//   0: spikes float32 [8,600,30000]   1: experimental_fanos_mean float32 [16]
//   2: sample_trials int32 [50]       3: sample_ids int32 [50,200]
//   4: sample_mask float32 [50,200]   out: float32 scalar
// ---------------------------------------------------------------------------
extern "C" void kernel_launch(void* const* d_in, const int* in_sizes, int n_in,
                              void* d_out, int out_size)
{
    const float* spikes = (const float*)d_in[0];
    const float* expf_  = (const float*)d_in[1];
    const int*   trials = (const int*)d_in[2];
    const int*   ids    = (const int*)d_in[3];
    const float* mask   = (const float*)d_in[4];
    float*       out    = (float*)d_out;

    dim3 grid(N_SAMPLES, (T_USE + 127) / 128, NJ);
    gather_kernel<<<grid, 128>>>(spikes, trials, ids, mask);
    fano_kernel<<<N_SAMPLES, 256>>>(expf_, out);
}